// round 5
// baseline (speedup 1.0000x reference)
#include <cuda_runtime.h>
#include <cuda_bf16.h>
#include <cstdint>

// ---------------------------------------------------------------------------
// Problem constants
// ---------------------------------------------------------------------------
#define NIMG   64
#define IMGS   224
#define GDIM   14
#define PSZ    16
#define DDIM   768
#define KCLS   768            // per-class K = 16*16*3
#define ROWEL  (IMGS*3)       // 672 elements per image row
#define IMG_ELEMS (NIMG * IMGS * IMGS * 3)   // 9,633,792

// GEMM tiling
#define BM      64
#define BN      128
#define BK      32
#define NCHUNKS (KCLS / BK)   // 24

// Scratch: split images (2 x 18.4 MB) + split class weights (2 x 10.6 MB)
__device__ __align__(16) __nv_bfloat16 g_img_hi[IMG_ELEMS];
__device__ __align__(16) __nv_bfloat16 g_img_lo[IMG_ELEMS];
__device__ __align__(16) __nv_bfloat16 g_Bhi[9u * KCLS * DDIM];
__device__ __align__(16) __nv_bfloat16 g_Blo[9u * KCLS * DDIM];

// ---------------------------------------------------------------------------
// helpers
// ---------------------------------------------------------------------------
__device__ __forceinline__ uint32_t smem_u32(const void* p) {
    uint32_t a;
    asm("{ .reg .u64 t; cvta.to.shared.u64 t, %1; cvt.u32.u64 %0, t; }"
        : "=r"(a) : "l"(p));
    return a;
}

__device__ __forceinline__ void mma_bf16(float* c, const uint32_t* a, const uint32_t* b) {
    asm volatile(
        "mma.sync.aligned.m16n8k16.row.col.f32.bf16.bf16.f32 "
        "{%0,%1,%2,%3}, {%4,%5,%6,%7}, {%8,%9}, {%0,%1,%2,%3};"
        : "+f"(c[0]), "+f"(c[1]), "+f"(c[2]), "+f"(c[3])
        : "r"(a[0]), "r"(a[1]), "r"(a[2]), "r"(a[3]), "r"(b[0]), "r"(b[1]));
}

__device__ __forceinline__ void ldsm_x4(uint32_t* r, uint32_t addr) {
    asm volatile("ldmatrix.sync.aligned.m8n8.x4.shared.b16 {%0,%1,%2,%3}, [%4];"
                 : "=r"(r[0]), "=r"(r[1]), "=r"(r[2]), "=r"(r[3]) : "r"(addr));
}

__device__ __forceinline__ void ldsm_x2t(uint32_t* r, uint32_t addr) {
    asm volatile("ldmatrix.sync.aligned.m8n8.x2.trans.shared.b16 {%0,%1}, [%2];"
                 : "=r"(r[0]), "=r"(r[1]) : "r"(addr));
}

#define CP_ASYNC16(dst, src) \
    asm volatile("cp.async.cg.shared.global [%0], [%1], 16;" :: "r"(dst), "l"(src))
#define CP_COMMIT() asm volatile("cp.async.commit_group;" ::: "memory")
#define CP_WAIT0()  asm volatile("cp.async.wait_group 0;" ::: "memory")

__device__ __forceinline__ void split_pack(float a, float b,
                                           uint32_t& hi, uint32_t& lo) {
    __nv_bfloat16 ha = __float2bfloat16_rn(a);
    __nv_bfloat16 hb = __float2bfloat16_rn(b);
    __nv_bfloat16 la = __float2bfloat16_rn(a - __bfloat162float(ha));
    __nv_bfloat16 lb = __float2bfloat16_rn(b - __bfloat162float(hb));
    hi = ((uint32_t)__bfloat16_as_ushort(hb) << 16) | __bfloat16_as_ushort(ha);
    lo = ((uint32_t)__bfloat16_as_ushort(lb) << 16) | __bfloat16_as_ushort(la);
}

// ---------------------------------------------------------------------------
// Kernel 0: split images into bf16 hi/lo arrays (same HWC indexing).
// ---------------------------------------------------------------------------
__global__ void split_img_kernel(const float* __restrict__ img) {
    int i = blockIdx.x * blockDim.x + threadIdx.x;   // float4 index
    float4 v = reinterpret_cast<const float4*>(img)[i];
    uint32_t h0, l0, h1, l1;
    split_pack(v.x, v.y, h0, l0);
    split_pack(v.z, v.w, h1, l1);
    reinterpret_cast<uint2*>(g_img_hi)[i] = make_uint2(h0, h1);
    reinterpret_cast<uint2*>(g_img_lo)[i] = make_uint2(l0, l1);
}

// ---------------------------------------------------------------------------
// Kernel 1: per-class effective weights, bf16 hi/lo split, layout [cls][k][n].
// One block per k-row; each thread covers 2 n for ALL 9 classes (reads W once).
// ---------------------------------------------------------------------------
__global__ void build_w_kernel(const float* __restrict__ W) {
    int k    = blockIdx.x;            // 0..767
    int pp   = k / 3,  cin = k % 3;
    int ph   = pp >> 4, pw = pp & 15;
    int n    = threadIdx.x * 2;

    const float* wb = W + (size_t)(pp * 15 + cin) * DDIM + n;
    float w0a = wb[0],          w0b = wb[1];
    float w1a = wb[3 * DDIM],   w1b = wb[3 * DDIM + 1];
    float w2a = wb[6 * DDIM],   w2b = wb[6 * DDIM + 1];
    float w3a = wb[9 * DDIM],   w3b = wb[9 * DDIM + 1];
    float w4a = wb[12 * DDIM],  w4b = wb[12 * DDIM + 1];

    #pragma unroll
    for (int cls = 0; cls < 9; cls++) {
        int clsH = cls / 3, clsW = cls % 3;
        int th = (clsH == 0 && ph < 8) ? 0 : (clsH == 2 && ph >= 8) ? 2 : 1;
        int tw = (clsW == 0 && pw < 8) ? 0 : (clsW == 2 && pw >= 8) ? 2 : 1;
        float s0 = w0a, s1 = w0b;
        if (!(th == 2 || tw == 2)) { s0 += w1a; s1 += w1b; }
        if (!(th == 0 || tw == 2)) { s0 += w2a; s1 += w2b; }
        if (!(th == 2 || tw == 0)) { s0 += w3a; s1 += w3b; }
        if (!(th == 0 || tw == 0)) { s0 += w4a; s1 += w4b; }
        uint32_t hi, lo;
        split_pack(s0, s1, hi, lo);
        size_t o = ((size_t)cls * KCLS + k) * DDIM + n;
        *reinterpret_cast<uint32_t*>(&g_Bhi[o]) = hi;
        *reinterpret_cast<uint32_t*>(&g_Blo[o]) = lo;
    }
}

// ---------------------------------------------------------------------------
// Kernel 2: class-partitioned bf16-split HMMA GEMM, all-cp.async pipeline.
// CTA tile 64x128x768, BK=32 double-buffered, 8 warps (2m x 4n), warp 32x32.
// 196 M-tiles x 6 N-tiles = 1176 CTAs (3.97 waves at 2 CTA/SM) — all full.
// ---------------------------------------------------------------------------
#define A_STRIDE_B 80     // bytes per A smem row (32 bf16 + 8 pad)
#define B_STRIDE_B 272    // bytes per B smem row (128 bf16 + 8 pad)
#define OFF_AHI 0
#define OFF_ALO 5120
#define OFF_BHI 10240
#define OFF_BLO 18944
#define STG     27648
#define SMEM_TOTAL (2 * STG)   // 55296

__global__ __launch_bounds__(256, 2)
void class_gemm_hmma(const float* __restrict__ bias,
                     float* __restrict__ out) {
    extern __shared__ __align__(16) char smem[];
    const uint32_t sb = smem_u32(smem);

    const int nhv[3]  = {1, 12, 1};
    const int ghbv[3] = {0, 1, 13};

    // map blockIdx.x -> (class, local m-tile); Mc always divisible by BM=64
    int mtl = blockIdx.x;
    int cls = 8;
    #pragma unroll
    for (int c = 0; c < 9; c++) {
        int tiles_c = (NIMG * nhv[c / 3] * nhv[c % 3]) / BM;
        if (mtl < tiles_c) { cls = c; break; }
        mtl -= tiles_c;
    }
    const int clsH = cls / 3, clsW = cls % 3;
    const int nw  = nhv[clsW];
    const int ghb = ghbv[clsH], gwb = ghbv[clsW];
    const int rpi = nhv[clsH] * nw;
    const int m0  = mtl * BM;
    const int n0  = blockIdx.y * BN;

    const int t    = threadIdx.x;
    const int wid  = t >> 5, lane = t & 31;
    const int wm   = wid >> 2;        // 0..1 (m)
    const int wn   = wid & 3;         // 0..3 (n)
    const int gi   = lane >> 2;
    const int li   = lane & 3;
    const int l16  = lane & 15;
    const int lhi  = (lane >> 4) & 1;

    // ---- A cp.async mapping: 1 segment per thread per part ----
    const int arow = t >> 2;          // 0..63
    const int aseg = t & 3;           // 16B = 8 k-elems
    uint32_t abase;
    {
        int am   = m0 + arow;
        int bimg = am / rpi;
        int r    = am % rpi;
        int gh   = ghb + r / nw;
        int gw   = gwb + r % nw;
        abase = (uint32_t)((bimg * IMGS + gh * PSZ) * ROWEL + gw * (PSZ * 3));
    }

    const __nv_bfloat16* gBhi = g_Bhi + ((size_t)cls * KCLS) * DDIM + n0;
    const ptrdiff_t bLoOff = g_Blo - g_Bhi;
    const ptrdiff_t iLoOff = g_img_lo - g_img_hi;

    // ldmatrix base offsets
    const uint32_t a_ld = (uint32_t)((wm * 32 + l16) * A_STRIDE_B + lhi * 16);
    const uint32_t b_ld = (uint32_t)(l16 * B_STRIDE_B + wn * 64);

    float acc[2][4][4];
    #pragma unroll
    for (int i = 0; i < 2; i++)
        #pragma unroll
        for (int j = 0; j < 4; j++)
            #pragma unroll
            for (int q = 0; q < 4; q++) acc[i][j][q] = 0.f;

    // ---------------- async tile loader ----------------
    auto issue_loads = [&](int c, int buf) {
        const int kt = c * BK;
        uint32_t dst = sb + buf * STG;
        // A: hi + lo
        {
            int k   = kt + aseg * 8;
            int phh = k / 48;
            int rem = k - phh * 48;
            const __nv_bfloat16* src = g_img_hi + abase + phh * ROWEL + rem;
            uint32_t doff = (uint32_t)(arow * A_STRIDE_B + aseg * 16);
            CP_ASYNC16(dst + OFF_AHI + doff, src);
            CP_ASYNC16(dst + OFF_ALO + doff, src + iLoOff);
        }
        // B: hi + lo
        #pragma unroll
        for (int i = 0; i < 2; i++) {
            int idx = i * 256 + t;
            int row = idx >> 4;
            int seg = idx & 15;
            const __nv_bfloat16* src = gBhi + (size_t)(kt + row) * DDIM + seg * 8;
            uint32_t doff = (uint32_t)(row * B_STRIDE_B + seg * 16);
            CP_ASYNC16(dst + OFF_BHI + doff, src);
            CP_ASYNC16(dst + OFF_BLO + doff, src + bLoOff);
        }
        CP_COMMIT();
    };

    // ---------------- pipeline ----------------
    issue_loads(0, 0);

    for (int c = 0; c < NCHUNKS; c++) {
        int buf = c & 1;
        CP_WAIT0();
        __syncthreads();
        if (c + 1 < NCHUNKS) issue_loads(c + 1, buf ^ 1);

        uint32_t stg = sb + buf * STG;
        #pragma unroll
        for (int ks = 0; ks < 2; ks++) {
            uint32_t bHi[4][2], bLo[4][2];
            #pragma unroll
            for (int nf = 0; nf < 4; nf++) {
                uint32_t bo = stg + b_ld + (uint32_t)(ks * 16 * B_STRIDE_B + nf * 16);
                ldsm_x2t(bHi[nf], bo + OFF_BHI);
                ldsm_x2t(bLo[nf], bo + OFF_BLO);
            }
            #pragma unroll
            for (int mf = 0; mf < 2; mf++) {
                uint32_t aHi[4], aLo[4];
                uint32_t ao = stg + a_ld + (uint32_t)(mf * 16 * A_STRIDE_B + ks * 32);
                ldsm_x4(aHi, ao + OFF_AHI);
                ldsm_x4(aLo, ao + OFF_ALO);
                #pragma unroll
                for (int nf = 0; nf < 4; nf++) {
                    mma_bf16(acc[mf][nf], aHi, bHi[nf]);
                    mma_bf16(acc[mf][nf], aLo, bHi[nf]);
                    mma_bf16(acc[mf][nf], aHi, bLo[nf]);
                }
            }
        }
    }

    // ---------------- epilogue (no M-bounds checks: tiles are full) --------
    float2 bb[4];
    #pragma unroll
    for (int nf = 0; nf < 4; nf++)
        bb[nf] = *reinterpret_cast<const float2*>(bias + n0 + wn * 32 + nf * 8 + li * 2);

    #pragma unroll
    for (int mf = 0; mf < 2; mf++) {
        #pragma unroll
        for (int half = 0; half < 2; half++) {
            int m = m0 + wm * 32 + mf * 16 + gi + half * 8;
            int bimg = m / rpi;
            int r    = m % rpi;
            int gh   = ghb + r / nw;
            int gw   = gwb + r % nw;
            size_t obase = ((size_t)(bimg * (GDIM * GDIM) + gh * GDIM + gw)) * DDIM
                         + n0 + wn * 32 + li * 2;
            #pragma unroll
            for (int nf = 0; nf < 4; nf++) {
                float2 v;
                v.x = acc[mf][nf][half * 2 + 0] + bb[nf].x;
                v.y = acc[mf][nf][half * 2 + 1] + bb[nf].y;
                *reinterpret_cast<float2*>(out + obase + nf * 8) = v;
            }
        }
    }
}

// ---------------------------------------------------------------------------
extern "C" void kernel_launch(void* const* d_in, const int* in_sizes, int n_in,
                              void* d_out, int out_size) {
    const float* images = (const float*)d_in[0];
    const float* W      = (const float*)d_in[1];
    const float* bias   = (const float*)d_in[2];
    float* out          = (float*)d_out;

    cudaFuncSetAttribute(class_gemm_hmma,
                         cudaFuncAttributeMaxDynamicSharedMemorySize, SMEM_TOTAL);

    split_img_kernel<<<IMG_ELEMS / 4 / 256, 256>>>(images);
    build_w_kernel<<<KCLS, 384>>>(W);

    // 196 M-tiles x 6 N-tiles
    dim3 grid(196, DDIM / BN);
    class_gemm_hmma<<<grid, 256, SMEM_TOTAL>>>(bias, out);
}

// round 6
// speedup vs baseline: 1.4431x; 1.4431x over previous
#include <cuda_runtime.h>
#include <cuda_fp16.h>
#include <cstdint>

// ---------------------------------------------------------------------------
// Problem constants
// ---------------------------------------------------------------------------
#define NIMG   64
#define IMGS   224
#define GDIM   14
#define PSZ    16
#define DDIM   768
#define KCLS   768            // per-class K = 16*16*3
#define ROWEL  (IMGS*3)       // 672 elements per image row
#define IMG_ELEMS (NIMG * IMGS * IMGS * 3)   // 9,633,792

// GEMM tiling
#define BM      128
#define BN      128
#define BK      32
#define NCHUNKS (KCLS / BK)   // 24

// Scratch: fp16 images (18.4 MB) + fp16 split class weights (2 x 10.6 MB)
__device__ __align__(16) __half g_img_h[IMG_ELEMS];
__device__ __align__(16) __half g_Bhi[9u * KCLS * DDIM];
__device__ __align__(16) __half g_Blo[9u * KCLS * DDIM];

// ---------------------------------------------------------------------------
// helpers
// ---------------------------------------------------------------------------
__device__ __forceinline__ uint32_t smem_u32(const void* p) {
    uint32_t a;
    asm("{ .reg .u64 t; cvta.to.shared.u64 t, %1; cvt.u32.u64 %0, t; }"
        : "=r"(a) : "l"(p));
    return a;
}

__device__ __forceinline__ void mma_f16(float* c, const uint32_t* a, const uint32_t* b) {
    asm volatile(
        "mma.sync.aligned.m16n8k16.row.col.f32.f16.f16.f32 "
        "{%0,%1,%2,%3}, {%4,%5,%6,%7}, {%8,%9}, {%0,%1,%2,%3};"
        : "+f"(c[0]), "+f"(c[1]), "+f"(c[2]), "+f"(c[3])
        : "r"(a[0]), "r"(a[1]), "r"(a[2]), "r"(a[3]), "r"(b[0]), "r"(b[1]));
}

__device__ __forceinline__ void ldsm_x4(uint32_t* r, uint32_t addr) {
    asm volatile("ldmatrix.sync.aligned.m8n8.x4.shared.b16 {%0,%1,%2,%3}, [%4];"
                 : "=r"(r[0]), "=r"(r[1]), "=r"(r[2]), "=r"(r[3]) : "r"(addr));
}

__device__ __forceinline__ void ldsm_x2t(uint32_t* r, uint32_t addr) {
    asm volatile("ldmatrix.sync.aligned.m8n8.x2.trans.shared.b16 {%0,%1}, [%2];"
                 : "=r"(r[0]), "=r"(r[1]) : "r"(addr));
}

#define CP_ASYNC16(dst, src) \
    asm volatile("cp.async.cg.shared.global [%0], [%1], 16;" :: "r"(dst), "l"(src))
#define CP_COMMIT() asm volatile("cp.async.commit_group;" ::: "memory")
#define CP_WAIT0()  asm volatile("cp.async.wait_group 0;" ::: "memory")

// fp16 2-way split pack (for weights)
__device__ __forceinline__ void split_pack_h(float a, float b,
                                             uint32_t& hi, uint32_t& lo) {
    __half ha = __float2half_rn(a);
    __half hb = __float2half_rn(b);
    __half la = __float2half_rn(a - __half2float(ha));
    __half lb = __float2half_rn(b - __half2float(hb));
    hi = ((uint32_t)__half_as_ushort(hb) << 16) | __half_as_ushort(ha);
    lo = ((uint32_t)__half_as_ushort(lb) << 16) | __half_as_ushort(la);
}

// ---------------------------------------------------------------------------
// Kernel 0: convert images to fp16 (same HWC indexing).
// ---------------------------------------------------------------------------
__global__ void conv_img_kernel(const float* __restrict__ img) {
    int i = blockIdx.x * blockDim.x + threadIdx.x;   // float4 index
    float4 v = reinterpret_cast<const float4*>(img)[i];
    uint32_t p0 = ((uint32_t)__half_as_ushort(__float2half_rn(v.y)) << 16)
                | __half_as_ushort(__float2half_rn(v.x));
    uint32_t p1 = ((uint32_t)__half_as_ushort(__float2half_rn(v.w)) << 16)
                | __half_as_ushort(__float2half_rn(v.z));
    reinterpret_cast<uint2*>(g_img_h)[i] = make_uint2(p0, p1);
}

// ---------------------------------------------------------------------------
// Kernel 1: per-class effective weights, fp16 hi/lo split, layout [cls][k][n].
// One block per k-row; each thread covers 2 n for ALL 9 classes (reads W once).
// ---------------------------------------------------------------------------
__global__ void build_w_kernel(const float* __restrict__ W) {
    int k    = blockIdx.x;            // 0..767
    int pp   = k / 3,  cin = k % 3;
    int ph   = pp >> 4, pw = pp & 15;
    int n    = threadIdx.x * 2;

    const float* wb = W + (size_t)(pp * 15 + cin) * DDIM + n;
    float w0a = wb[0],          w0b = wb[1];
    float w1a = wb[3 * DDIM],   w1b = wb[3 * DDIM + 1];
    float w2a = wb[6 * DDIM],   w2b = wb[6 * DDIM + 1];
    float w3a = wb[9 * DDIM],   w3b = wb[9 * DDIM + 1];
    float w4a = wb[12 * DDIM],  w4b = wb[12 * DDIM + 1];

    #pragma unroll
    for (int cls = 0; cls < 9; cls++) {
        int clsH = cls / 3, clsW = cls % 3;
        int th = (clsH == 0 && ph < 8) ? 0 : (clsH == 2 && ph >= 8) ? 2 : 1;
        int tw = (clsW == 0 && pw < 8) ? 0 : (clsW == 2 && pw >= 8) ? 2 : 1;
        float s0 = w0a, s1 = w0b;
        if (!(th == 2 || tw == 2)) { s0 += w1a; s1 += w1b; }
        if (!(th == 0 || tw == 2)) { s0 += w2a; s1 += w2b; }
        if (!(th == 2 || tw == 0)) { s0 += w3a; s1 += w3b; }
        if (!(th == 0 || tw == 0)) { s0 += w4a; s1 += w4b; }
        uint32_t hi, lo;
        split_pack_h(s0, s1, hi, lo);
        size_t o = ((size_t)cls * KCLS + k) * DDIM + n;
        *reinterpret_cast<uint32_t*>(&g_Bhi[o]) = hi;
        *reinterpret_cast<uint32_t*>(&g_Blo[o]) = lo;
    }
}

// ---------------------------------------------------------------------------
// Kernel 2: class-partitioned fp16 HMMA GEMM (A plain fp16, B hi/lo split).
// CTA tile 128x128x768, BK=32 double-buffered, 8 warps (2m x 4n), warp 64x32.
// 100 M-tiles x 6 N-tiles = 600 CTAs, 2 CTAs/SM.
// ---------------------------------------------------------------------------
#define A_STRIDE_B 80     // bytes per A smem row (32 fp16 + 8 pad)
#define B_STRIDE_B 272    // bytes per B smem row (128 fp16 + 8 pad)
#define OFF_A   0
#define OFF_BHI 10240
#define OFF_BLO 18944
#define STG     27648
#define SMEM_TOTAL (2 * STG)   // 55296

__global__ __launch_bounds__(256, 2)
void class_gemm_hmma(const float* __restrict__ bias,
                     float* __restrict__ out) {
    extern __shared__ __align__(16) char smem[];
    const uint32_t sb = smem_u32(smem);

    const int nhv[3]  = {1, 12, 1};
    const int ghbv[3] = {0, 1, 13};

    // map blockIdx.x -> (class, local m-tile)
    int mtl = blockIdx.x;
    int cls = 8;
    #pragma unroll
    for (int c = 0; c < 9; c++) {
        int tiles_c = (NIMG * nhv[c / 3] * nhv[c % 3] + BM - 1) / BM;
        if (mtl < tiles_c) { cls = c; break; }
        mtl -= tiles_c;
    }
    const int clsH = cls / 3, clsW = cls % 3;
    const int nw  = nhv[clsW];
    const int ghb = ghbv[clsH], gwb = ghbv[clsW];
    const int rpi = nhv[clsH] * nw;
    const int Mc  = NIMG * rpi;
    const int m0  = mtl * BM;
    const int n0  = blockIdx.y * BN;

    const int t    = threadIdx.x;
    const int wid  = t >> 5, lane = t & 31;
    const int wm   = wid >> 2;        // 0..1 (m)
    const int wn   = wid & 3;         // 0..3 (n)
    const int gi   = lane >> 2;
    const int li   = lane & 3;
    const int l16  = lane & 15;
    const int lhi  = (lane >> 4) & 1;

    // ---- A cp.async mapping: 2 segments per thread ----
    int arow_[2], aseg_[2];
    uint32_t abase_[2], asz_[2];
    #pragma unroll
    for (int i = 0; i < 2; i++) {
        int idx = i * 256 + t;
        int row = idx >> 2;
        arow_[i] = row;
        aseg_[i] = idx & 3;
        int am = m0 + row;
        bool v = am < Mc;
        int mm = v ? am : 0;
        int bimg = mm / rpi;
        int r    = mm % rpi;
        int gh   = ghb + r / nw;
        int gw   = gwb + r % nw;
        abase_[i] = (uint32_t)((bimg * IMGS + gh * PSZ) * ROWEL + gw * (PSZ * 3));
        asz_[i]   = v ? 16u : 0u;
    }

    const __half* gBhi = g_Bhi + ((size_t)cls * KCLS) * DDIM + n0;
    const ptrdiff_t bLoOff = g_Blo - g_Bhi;

    // ldmatrix base offsets
    const uint32_t a_ld = (uint32_t)((wm * 64 + l16) * A_STRIDE_B + lhi * 16);
    const uint32_t b_ld = (uint32_t)(l16 * B_STRIDE_B + wn * 64);

    float acc[4][4][4];
    #pragma unroll
    for (int i = 0; i < 4; i++)
        #pragma unroll
        for (int j = 0; j < 4; j++)
            #pragma unroll
            for (int q = 0; q < 4; q++) acc[i][j][q] = 0.f;

    // ---------------- async tile loader ----------------
    auto issue_loads = [&](int c, int buf) {
        const int kt = c * BK;
        uint32_t dst = sb + buf * STG;
        // A (plain fp16)
        #pragma unroll
        for (int i = 0; i < 2; i++) {
            int k   = kt + aseg_[i] * 8;
            int phh = k / 48;
            int rem = k - phh * 48;
            const __half* src = g_img_h + abase_[i] + phh * ROWEL + rem;
            uint32_t doff = (uint32_t)(arow_[i] * A_STRIDE_B + aseg_[i] * 16);
            asm volatile("cp.async.cg.shared.global [%0], [%1], 16, %2;"
                         :: "r"(dst + OFF_A + doff), "l"(src), "r"(asz_[i]));
        }
        // B: hi + lo
        #pragma unroll
        for (int i = 0; i < 2; i++) {
            int idx = i * 256 + t;
            int row = idx >> 4;
            int seg = idx & 15;
            const __half* src = gBhi + (size_t)(kt + row) * DDIM + seg * 8;
            uint32_t doff = (uint32_t)(row * B_STRIDE_B + seg * 16);
            CP_ASYNC16(dst + OFF_BHI + doff, src);
            CP_ASYNC16(dst + OFF_BLO + doff, src + bLoOff);
        }
        CP_COMMIT();
    };

    // ---------------- pipeline ----------------
    issue_loads(0, 0);

    for (int c = 0; c < NCHUNKS; c++) {
        int buf = c & 1;
        CP_WAIT0();
        __syncthreads();
        if (c + 1 < NCHUNKS) issue_loads(c + 1, buf ^ 1);

        uint32_t stg = sb + buf * STG;
        #pragma unroll
        for (int ks = 0; ks < 2; ks++) {
            uint32_t bHi[4][2], bLo[4][2];
            #pragma unroll
            for (int nf = 0; nf < 4; nf++) {
                uint32_t bo = stg + b_ld + (uint32_t)(ks * 16 * B_STRIDE_B + nf * 16);
                ldsm_x2t(bHi[nf], bo + OFF_BHI);
                ldsm_x2t(bLo[nf], bo + OFF_BLO);
            }
            #pragma unroll
            for (int mf = 0; mf < 4; mf++) {
                uint32_t aF[4];
                uint32_t ao = stg + a_ld + (uint32_t)(mf * 16 * A_STRIDE_B + ks * 32);
                ldsm_x4(aF, ao + OFF_A);
                #pragma unroll
                for (int nf = 0; nf < 4; nf++) {
                    mma_f16(acc[mf][nf], aF, bHi[nf]);
                    mma_f16(acc[mf][nf], aF, bLo[nf]);
                }
            }
        }
    }

    // ---------------- epilogue ----------------
    float2 bb[4];
    #pragma unroll
    for (int nf = 0; nf < 4; nf++)
        bb[nf] = *reinterpret_cast<const float2*>(bias + n0 + wn * 32 + nf * 8 + li * 2);

    #pragma unroll
    for (int mf = 0; mf < 4; mf++) {
        #pragma unroll
        for (int half = 0; half < 2; half++) {
            int m = m0 + wm * 64 + mf * 16 + gi + half * 8;
            if (m < Mc) {
                int bimg = m / rpi;
                int r    = m % rpi;
                int gh   = ghb + r / nw;
                int gw   = gwb + r % nw;
                size_t obase = ((size_t)(bimg * (GDIM * GDIM) + gh * GDIM + gw)) * DDIM
                             + n0 + wn * 32 + li * 2;
                #pragma unroll
                for (int nf = 0; nf < 4; nf++) {
                    float2 v;
                    v.x = acc[mf][nf][half * 2 + 0] + bb[nf].x;
                    v.y = acc[mf][nf][half * 2 + 1] + bb[nf].y;
                    *reinterpret_cast<float2*>(out + obase + nf * 8) = v;
                }
            }
        }
    }
}

// ---------------------------------------------------------------------------
extern "C" void kernel_launch(void* const* d_in, const int* in_sizes, int n_in,
                              void* d_out, int out_size) {
    const float* images = (const float*)d_in[0];
    const float* W      = (const float*)d_in[1];
    const float* bias   = (const float*)d_in[2];
    float* out          = (float*)d_out;

    cudaFuncSetAttribute(class_gemm_hmma,
                         cudaFuncAttributeMaxDynamicSharedMemorySize, SMEM_TOTAL);

    conv_img_kernel<<<IMG_ELEMS / 4 / 256, 256>>>(images);
    build_w_kernel<<<KCLS, 384>>>(W);

    // 100 M-tiles x 6 N-tiles
    dim3 grid(100, DDIM / BN);
    class_gemm_hmma<<<grid, 256, SMEM_TOTAL>>>(bias, out);
}

// round 7
// speedup vs baseline: 2.0579x; 1.4260x over previous
#include <cuda_runtime.h>
#include <cuda_fp16.h>
#include <cstdint>

// ---------------------------------------------------------------------------
// Problem constants
// ---------------------------------------------------------------------------
#define NIMG   64
#define IMGS   224
#define GDIM   14
#define PSZ    16
#define DDIM   768
#define KCLS   768            // per-class K = 16*16*3
#define ROWEL  (IMGS*3)       // 672 elements per image row
#define IMG_ELEMS (NIMG * IMGS * IMGS * 3)   // 9,633,792

// GEMM tiling
#define BM      128
#define BN      128
#define BK      32
#define NCHUNKS (KCLS / BK)   // 24

// Scratch: fp16 images (18.4 MB) + fp16 class weights (10.6 MB)
__device__ __align__(16) __half g_img_h[IMG_ELEMS];
__device__ __align__(16) __half g_Bh[9u * KCLS * DDIM];

// ---------------------------------------------------------------------------
// helpers
// ---------------------------------------------------------------------------
__device__ __forceinline__ uint32_t smem_u32(const void* p) {
    uint32_t a;
    asm("{ .reg .u64 t; cvta.to.shared.u64 t, %1; cvt.u32.u64 %0, t; }"
        : "=r"(a) : "l"(p));
    return a;
}

__device__ __forceinline__ void mma_f16(float* c, const uint32_t* a, const uint32_t* b) {
    asm volatile(
        "mma.sync.aligned.m16n8k16.row.col.f32.f16.f16.f32 "
        "{%0,%1,%2,%3}, {%4,%5,%6,%7}, {%8,%9}, {%0,%1,%2,%3};"
        : "+f"(c[0]), "+f"(c[1]), "+f"(c[2]), "+f"(c[3])
        : "r"(a[0]), "r"(a[1]), "r"(a[2]), "r"(a[3]), "r"(b[0]), "r"(b[1]));
}

__device__ __forceinline__ void ldsm_x4(uint32_t* r, uint32_t addr) {
    asm volatile("ldmatrix.sync.aligned.m8n8.x4.shared.b16 {%0,%1,%2,%3}, [%4];"
                 : "=r"(r[0]), "=r"(r[1]), "=r"(r[2]), "=r"(r[3]) : "r"(addr));
}

__device__ __forceinline__ void ldsm_x2t(uint32_t* r, uint32_t addr) {
    asm volatile("ldmatrix.sync.aligned.m8n8.x2.trans.shared.b16 {%0,%1}, [%2];"
                 : "=r"(r[0]), "=r"(r[1]) : "r"(addr));
}

#define CP_ASYNC16(dst, src) \
    asm volatile("cp.async.cg.shared.global [%0], [%1], 16;" :: "r"(dst), "l"(src))
#define CP_COMMIT() asm volatile("cp.async.commit_group;" ::: "memory")
#define CP_WAIT1()  asm volatile("cp.async.wait_group 1;" ::: "memory")

// ---------------------------------------------------------------------------
// Kernel 0: convert images to fp16 (same HWC indexing).
// ---------------------------------------------------------------------------
__global__ void conv_img_kernel(const float* __restrict__ img) {
    int i = blockIdx.x * blockDim.x + threadIdx.x;   // float4 index
    float4 v = reinterpret_cast<const float4*>(img)[i];
    uint32_t p0 = ((uint32_t)__half_as_ushort(__float2half_rn(v.y)) << 16)
                | __half_as_ushort(__float2half_rn(v.x));
    uint32_t p1 = ((uint32_t)__half_as_ushort(__float2half_rn(v.w)) << 16)
                | __half_as_ushort(__float2half_rn(v.z));
    reinterpret_cast<uint2*>(g_img_h)[i] = make_uint2(p0, p1);
}

// ---------------------------------------------------------------------------
// Kernel 1: per-class effective weights, fp16, layout [cls][k][n].
// One block per k-row; each thread covers 2 n for ALL 9 classes (reads W once).
// ---------------------------------------------------------------------------
__global__ void build_w_kernel(const float* __restrict__ W) {
    int k    = blockIdx.x;            // 0..767
    int pp   = k / 3,  cin = k % 3;
    int ph   = pp >> 4, pw = pp & 15;
    int n    = threadIdx.x * 2;

    const float* wb = W + (size_t)(pp * 15 + cin) * DDIM + n;
    float w0a = wb[0],          w0b = wb[1];
    float w1a = wb[3 * DDIM],   w1b = wb[3 * DDIM + 1];
    float w2a = wb[6 * DDIM],   w2b = wb[6 * DDIM + 1];
    float w3a = wb[9 * DDIM],   w3b = wb[9 * DDIM + 1];
    float w4a = wb[12 * DDIM],  w4b = wb[12 * DDIM + 1];

    #pragma unroll
    for (int cls = 0; cls < 9; cls++) {
        int clsH = cls / 3, clsW = cls % 3;
        int th = (clsH == 0 && ph < 8) ? 0 : (clsH == 2 && ph >= 8) ? 2 : 1;
        int tw = (clsW == 0 && pw < 8) ? 0 : (clsW == 2 && pw >= 8) ? 2 : 1;
        float s0 = w0a, s1 = w0b;
        if (!(th == 2 || tw == 2)) { s0 += w1a; s1 += w1b; }
        if (!(th == 0 || tw == 2)) { s0 += w2a; s1 += w2b; }
        if (!(th == 2 || tw == 0)) { s0 += w3a; s1 += w3b; }
        if (!(th == 0 || tw == 0)) { s0 += w4a; s1 += w4b; }
        uint32_t hv = ((uint32_t)__half_as_ushort(__float2half_rn(s1)) << 16)
                    | __half_as_ushort(__float2half_rn(s0));
        size_t o = ((size_t)cls * KCLS + k) * DDIM + n;
        *reinterpret_cast<uint32_t*>(&g_Bh[o]) = hv;
    }
}

// ---------------------------------------------------------------------------
// Kernel 2: class-partitioned fp16 HMMA GEMM (plain fp16 A and B).
// CTA tile 128x128x768, BK=32, 3-stage cp.async pipeline, 8 warps (2m x 4n).
// 100 M-tiles x 6 N-tiles = 600 CTAs, 2 CTAs/SM.
// ---------------------------------------------------------------------------
#define A_STRIDE_B 80     // bytes per A smem row (32 fp16 + 8 pad)
#define B_STRIDE_B 272    // bytes per B smem row (128 fp16 + 8 pad)
#define OFF_A   0
#define OFF_B   10240
#define STG     18944
#define NSTAGE  3
#define SMEM_TOTAL (NSTAGE * STG)   // 56832

__global__ __launch_bounds__(256, 2)
void class_gemm_hmma(const float* __restrict__ bias,
                     float* __restrict__ out) {
    extern __shared__ __align__(16) char smem[];
    const uint32_t sb = smem_u32(smem);

    const int nhv[3]  = {1, 12, 1};
    const int ghbv[3] = {0, 1, 13};

    // map blockIdx.x -> (class, local m-tile)
    int mtl = blockIdx.x;
    int cls = 8;
    #pragma unroll
    for (int c = 0; c < 9; c++) {
        int tiles_c = (NIMG * nhv[c / 3] * nhv[c % 3] + BM - 1) / BM;
        if (mtl < tiles_c) { cls = c; break; }
        mtl -= tiles_c;
    }
    const int clsH = cls / 3, clsW = cls % 3;
    const int nw  = nhv[clsW];
    const int ghb = ghbv[clsH], gwb = ghbv[clsW];
    const int rpi = nhv[clsH] * nw;
    const int Mc  = NIMG * rpi;
    const int m0  = mtl * BM;
    const int n0  = blockIdx.y * BN;

    const int t    = threadIdx.x;
    const int wid  = t >> 5, lane = t & 31;
    const int wm   = wid >> 2;        // 0..1 (m)
    const int wn   = wid & 3;         // 0..3 (n)
    const int gi   = lane >> 2;
    const int li   = lane & 3;
    const int l16  = lane & 15;
    const int lhi  = (lane >> 4) & 1;

    // ---- A cp.async mapping: 2 segments per thread ----
    int arow_[2], aseg_[2];
    uint32_t abase_[2], asz_[2];
    #pragma unroll
    for (int i = 0; i < 2; i++) {
        int idx = i * 256 + t;
        int row = idx >> 2;
        arow_[i] = row;
        aseg_[i] = idx & 3;
        int am = m0 + row;
        bool v = am < Mc;
        int mm = v ? am : 0;
        int bimg = mm / rpi;
        int r    = mm % rpi;
        int gh   = ghb + r / nw;
        int gw   = gwb + r % nw;
        abase_[i] = (uint32_t)((bimg * IMGS + gh * PSZ) * ROWEL + gw * (PSZ * 3));
        asz_[i]   = v ? 16u : 0u;
    }

    const __half* gB = g_Bh + ((size_t)cls * KCLS) * DDIM + n0;

    // ldmatrix base offsets
    const uint32_t a_ld = (uint32_t)((wm * 64 + l16) * A_STRIDE_B + lhi * 16);
    const uint32_t b_ld = (uint32_t)(l16 * B_STRIDE_B + wn * 64);

    float acc[4][4][4];
    #pragma unroll
    for (int i = 0; i < 4; i++)
        #pragma unroll
        for (int j = 0; j < 4; j++)
            #pragma unroll
            for (int q = 0; q < 4; q++) acc[i][j][q] = 0.f;

    // ---------------- async tile loader ----------------
    auto issue_loads = [&](int c) {
        const int kt  = c * BK;
        const int buf = c % NSTAGE;
        uint32_t dst = sb + buf * STG;
        // A (plain fp16)
        #pragma unroll
        for (int i = 0; i < 2; i++) {
            int k   = kt + aseg_[i] * 8;
            int phh = k / 48;
            int rem = k - phh * 48;
            const __half* src = g_img_h + abase_[i] + phh * ROWEL + rem;
            uint32_t doff = (uint32_t)(arow_[i] * A_STRIDE_B + aseg_[i] * 16);
            asm volatile("cp.async.cg.shared.global [%0], [%1], 16, %2;"
                         :: "r"(dst + OFF_A + doff), "l"(src), "r"(asz_[i]));
        }
        // B
        #pragma unroll
        for (int i = 0; i < 2; i++) {
            int idx = i * 256 + t;
            int row = idx >> 4;
            int seg = idx & 15;
            const __half* src = gB + (size_t)(kt + row) * DDIM + seg * 8;
            uint32_t doff = (uint32_t)(row * B_STRIDE_B + seg * 16);
            CP_ASYNC16(dst + OFF_B + doff, src);
        }
        CP_COMMIT();
    };

    // ---------------- pipeline (3-stage, 2 groups in flight) ----------------
    issue_loads(0);
    issue_loads(1);

    for (int c = 0; c < NCHUNKS; c++) {
        CP_WAIT1();          // group c complete (c+1 still in flight)
        __syncthreads();
        if (c + 2 < NCHUNKS) issue_loads(c + 2);

        uint32_t stg = sb + (c % NSTAGE) * STG;
        #pragma unroll
        for (int ks = 0; ks < 2; ks++) {
            uint32_t bF[4][2];
            #pragma unroll
            for (int nf = 0; nf < 4; nf++) {
                uint32_t bo = stg + b_ld + (uint32_t)(ks * 16 * B_STRIDE_B + nf * 16);
                ldsm_x2t(bF[nf], bo + OFF_B);
            }
            #pragma unroll
            for (int mf = 0; mf < 4; mf++) {
                uint32_t aF[4];
                uint32_t ao = stg + a_ld + (uint32_t)(mf * 16 * A_STRIDE_B + ks * 32);
                ldsm_x4(aF, ao + OFF_A);
                #pragma unroll
                for (int nf = 0; nf < 4; nf++)
                    mma_f16(acc[mf][nf], aF, bF[nf]);
            }
        }
        __syncthreads();
    }

    // ---------------- epilogue ----------------
    float2 bb[4];
    #pragma unroll
    for (int nf = 0; nf < 4; nf++)
        bb[nf] = *reinterpret_cast<const float2*>(bias + n0 + wn * 32 + nf * 8 + li * 2);

    #pragma unroll
    for (int mf = 0; mf < 4; mf++) {
        #pragma unroll
        for (int half = 0; half < 2; half++) {
            int m = m0 + wm * 64 + mf * 16 + gi + half * 8;
            if (m < Mc) {
                int bimg = m / rpi;
                int r    = m % rpi;
                int gh   = ghb + r / nw;
                int gw   = gwb + r % nw;
                size_t obase = ((size_t)(bimg * (GDIM * GDIM) + gh * GDIM + gw)) * DDIM
                             + n0 + wn * 32 + li * 2;
                #pragma unroll
                for (int nf = 0; nf < 4; nf++) {
                    float2 v;
                    v.x = acc[mf][nf][half * 2 + 0] + bb[nf].x;
                    v.y = acc[mf][nf][half * 2 + 1] + bb[nf].y;
                    *reinterpret_cast<float2*>(out + obase + nf * 8) = v;
                }
            }
        }
    }
}

// ---------------------------------------------------------------------------
extern "C" void kernel_launch(void* const* d_in, const int* in_sizes, int n_in,
                              void* d_out, int out_size) {
    const float* images = (const float*)d_in[0];
    const float* W      = (const float*)d_in[1];
    const float* bias   = (const float*)d_in[2];
    float* out          = (float*)d_out;

    cudaFuncSetAttribute(class_gemm_hmma,
                         cudaFuncAttributeMaxDynamicSharedMemorySize, SMEM_TOTAL);

    conv_img_kernel<<<IMG_ELEMS / 4 / 256, 256>>>(images);
    build_w_kernel<<<KCLS, 384>>>(W);

    // 100 M-tiles x 6 N-tiles
    dim3 grid(100, DDIM / BN);
    class_gemm_hmma<<<grid, 256, SMEM_TOTAL>>>(bias, out);
}

// round 8
// speedup vs baseline: 2.2213x; 1.0794x over previous
#include <cuda_runtime.h>
#include <cuda_fp16.h>
#include <cstdint>

// ---------------------------------------------------------------------------
// Problem constants
// ---------------------------------------------------------------------------
#define NIMG   64
#define IMGS   224
#define GDIM   14
#define PSZ    16
#define DDIM   768
#define KCLS   768            // per-class K = 16*16*3
#define ROWEL  (IMGS*3)       // 672 elements per image row
#define IMG_ELEMS (NIMG * IMGS * IMGS * 3)   // 9,633,792
#define CONV_BLOCKS (IMG_ELEMS / 4 / 256)    // 9408

// GEMM tiling
#define BM      128
#define BN      128
#define BK      32
#define NCHUNKS (KCLS / BK)   // 24

// Scratch: fp16 images (18.4 MB) + fp16 class weights (10.6 MB)
__device__ __align__(16) __half g_img_h[IMG_ELEMS];
__device__ __align__(16) __half g_Bh[9u * KCLS * DDIM];

// ---------------------------------------------------------------------------
// helpers
// ---------------------------------------------------------------------------
__device__ __forceinline__ uint32_t smem_u32(const void* p) {
    uint32_t a;
    asm("{ .reg .u64 t; cvta.to.shared.u64 t, %1; cvt.u32.u64 %0, t; }"
        : "=r"(a) : "l"(p));
    return a;
}

__device__ __forceinline__ void mma_f16(float* c, const uint32_t* a, const uint32_t* b) {
    asm volatile(
        "mma.sync.aligned.m16n8k16.row.col.f32.f16.f16.f32 "
        "{%0,%1,%2,%3}, {%4,%5,%6,%7}, {%8,%9}, {%0,%1,%2,%3};"
        : "+f"(c[0]), "+f"(c[1]), "+f"(c[2]), "+f"(c[3])
        : "r"(a[0]), "r"(a[1]), "r"(a[2]), "r"(a[3]), "r"(b[0]), "r"(b[1]));
}

__device__ __forceinline__ void ldsm_x4(uint32_t* r, uint32_t addr) {
    asm volatile("ldmatrix.sync.aligned.m8n8.x4.shared.b16 {%0,%1,%2,%3}, [%4];"
                 : "=r"(r[0]), "=r"(r[1]), "=r"(r[2]), "=r"(r[3]) : "r"(addr));
}

__device__ __forceinline__ void ldsm_x4t(uint32_t* r, uint32_t addr) {
    asm volatile("ldmatrix.sync.aligned.m8n8.x4.trans.shared.b16 {%0,%1,%2,%3}, [%4];"
                 : "=r"(r[0]), "=r"(r[1]), "=r"(r[2]), "=r"(r[3]) : "r"(addr));
}

#define CP_ASYNC16(dst, src) \
    asm volatile("cp.async.cg.shared.global [%0], [%1], 16;" :: "r"(dst), "l"(src))
#define CP_COMMIT() asm volatile("cp.async.commit_group;" ::: "memory")
#define CP_WAIT2()  asm volatile("cp.async.wait_group 2;" ::: "memory")

// ---------------------------------------------------------------------------
// Kernel 0 (fused prep): blocks [0, CONV_BLOCKS) convert images to fp16;
// blocks [CONV_BLOCKS, CONV_BLOCKS+768) build per-class fp16 weights
// (layout [cls][k][n], one block per k-row, thread covers n via stride loop).
// ---------------------------------------------------------------------------
__global__ void prep_kernel(const float* __restrict__ img,
                            const float* __restrict__ W) {
    if (blockIdx.x < CONV_BLOCKS) {
        int i = blockIdx.x * blockDim.x + threadIdx.x;   // float4 index
        float4 v = reinterpret_cast<const float4*>(img)[i];
        uint32_t p0 = ((uint32_t)__half_as_ushort(__float2half_rn(v.y)) << 16)
                    | __half_as_ushort(__float2half_rn(v.x));
        uint32_t p1 = ((uint32_t)__half_as_ushort(__float2half_rn(v.w)) << 16)
                    | __half_as_ushort(__float2half_rn(v.z));
        reinterpret_cast<uint2*>(g_img_h)[i] = make_uint2(p0, p1);
        return;
    }

    int k  = blockIdx.x - CONV_BLOCKS;   // 0..767
    int pp = k / 3,  cin = k % 3;
    int ph = pp >> 4, pw = pp & 15;

    for (int n = threadIdx.x * 2; n < DDIM; n += blockDim.x * 2) {
        const float* wb = W + (size_t)(pp * 15 + cin) * DDIM + n;
        float w0a = wb[0],          w0b = wb[1];
        float w1a = wb[3 * DDIM],   w1b = wb[3 * DDIM + 1];
        float w2a = wb[6 * DDIM],   w2b = wb[6 * DDIM + 1];
        float w3a = wb[9 * DDIM],   w3b = wb[9 * DDIM + 1];
        float w4a = wb[12 * DDIM],  w4b = wb[12 * DDIM + 1];

        #pragma unroll
        for (int cls = 0; cls < 9; cls++) {
            int clsH = cls / 3, clsW = cls % 3;
            int th = (clsH == 0 && ph < 8) ? 0 : (clsH == 2 && ph >= 8) ? 2 : 1;
            int tw = (clsW == 0 && pw < 8) ? 0 : (clsW == 2 && pw >= 8) ? 2 : 1;
            float s0 = w0a, s1 = w0b;
            if (!(th == 2 || tw == 2)) { s0 += w1a; s1 += w1b; }
            if (!(th == 0 || tw == 2)) { s0 += w2a; s1 += w2b; }
            if (!(th == 2 || tw == 0)) { s0 += w3a; s1 += w3b; }
            if (!(th == 0 || tw == 0)) { s0 += w4a; s1 += w4b; }
            uint32_t hv = ((uint32_t)__half_as_ushort(__float2half_rn(s1)) << 16)
                        | __half_as_ushort(__float2half_rn(s0));
            size_t o = ((size_t)cls * KCLS + k) * DDIM + n;
            *reinterpret_cast<uint32_t*>(&g_Bh[o]) = hv;
        }
    }
}

// ---------------------------------------------------------------------------
// Kernel 1: class-partitioned fp16 HMMA GEMM (plain fp16 A and B).
// CTA tile 128x128x768, BK=32, 4-stage cp.async pipeline, 8 warps (2m x 4n).
// 100 M-tiles x 6 N-tiles = 600 CTAs, 2 CTAs/SM.
// ---------------------------------------------------------------------------
#define A_STRIDE_B 80     // bytes per A smem row (32 fp16 + 8 pad)
#define B_STRIDE_B 272    // bytes per B smem row (128 fp16 + 8 pad)
#define OFF_A   0
#define OFF_B   10240
#define STG     18944
#define NSTAGE  4
#define SMEM_TOTAL (NSTAGE * STG)   // 75776

__global__ __launch_bounds__(256, 2)
void class_gemm_hmma(const float* __restrict__ bias,
                     float* __restrict__ out) {
    extern __shared__ __align__(16) char smem[];
    const uint32_t sb = smem_u32(smem);

    const int nhv[3]  = {1, 12, 1};
    const int ghbv[3] = {0, 1, 13};

    // map blockIdx.x -> (class, local m-tile)
    int mtl = blockIdx.x;
    int cls = 8;
    #pragma unroll
    for (int c = 0; c < 9; c++) {
        int tiles_c = (NIMG * nhv[c / 3] * nhv[c % 3] + BM - 1) / BM;
        if (mtl < tiles_c) { cls = c; break; }
        mtl -= tiles_c;
    }
    const int clsH = cls / 3, clsW = cls % 3;
    const int nw  = nhv[clsW];
    const int ghb = ghbv[clsH], gwb = ghbv[clsW];
    const int rpi = nhv[clsH] * nw;
    const int Mc  = NIMG * rpi;
    const int m0  = mtl * BM;
    const int n0  = blockIdx.y * BN;

    const int t    = threadIdx.x;
    const int wid  = t >> 5, lane = t & 31;
    const int wm   = wid >> 2;        // 0..1 (m)
    const int wn   = wid & 3;         // 0..3 (n)
    const int gi   = lane >> 2;
    const int li   = lane & 3;
    const int l16  = lane & 15;
    const int lhi  = (lane >> 4) & 1;

    // ---- A cp.async mapping: 2 segments per thread ----
    int arow_[2], aseg_[2];
    uint32_t abase_[2], asz_[2];
    #pragma unroll
    for (int i = 0; i < 2; i++) {
        int idx = i * 256 + t;
        int row = idx >> 2;
        arow_[i] = row;
        aseg_[i] = idx & 3;
        int am = m0 + row;
        bool v = am < Mc;
        int mm = v ? am : 0;
        int bimg = mm / rpi;
        int r    = mm % rpi;
        int gh   = ghb + r / nw;
        int gw   = gwb + r % nw;
        abase_[i] = (uint32_t)((bimg * IMGS + gh * PSZ) * ROWEL + gw * (PSZ * 3));
        asz_[i]   = v ? 16u : 0u;
    }

    const __half* gB = g_Bh + ((size_t)cls * KCLS) * DDIM + n0;

    // ldmatrix base offsets
    const uint32_t a_ld = (uint32_t)((wm * 64 + l16) * A_STRIDE_B + lhi * 16);
    // B x4.trans: lanes 0-15 -> rows k0..15 at col pair base, lanes 16-31 -> col +16B
    const uint32_t b_ld = (uint32_t)(l16 * B_STRIDE_B + wn * 64 + lhi * 16);

    float acc[4][4][4];
    #pragma unroll
    for (int i = 0; i < 4; i++)
        #pragma unroll
        for (int j = 0; j < 4; j++)
            #pragma unroll
            for (int q = 0; q < 4; q++) acc[i][j][q] = 0.f;

    // ---------------- async tile loader ----------------
    auto issue_loads = [&](int c) {
        const int kt  = c * BK;
        const int buf = c & (NSTAGE - 1);
        uint32_t dst = sb + buf * STG;
        // A (plain fp16)
        #pragma unroll
        for (int i = 0; i < 2; i++) {
            int k   = kt + aseg_[i] * 8;
            int phh = k / 48;
            int rem = k - phh * 48;
            const __half* src = g_img_h + abase_[i] + phh * ROWEL + rem;
            uint32_t doff = (uint32_t)(arow_[i] * A_STRIDE_B + aseg_[i] * 16);
            asm volatile("cp.async.cg.shared.global [%0], [%1], 16, %2;"
                         :: "r"(dst + OFF_A + doff), "l"(src), "r"(asz_[i]));
        }
        // B
        #pragma unroll
        for (int i = 0; i < 2; i++) {
            int idx = i * 256 + t;
            int row = idx >> 4;
            int seg = idx & 15;
            const __half* src = gB + (size_t)(kt + row) * DDIM + seg * 8;
            uint32_t doff = (uint32_t)(row * B_STRIDE_B + seg * 16);
            CP_ASYNC16(dst + OFF_B + doff, src);
        }
        CP_COMMIT();
    };

    // ---------------- pipeline (4-stage, 3 groups in flight) ----------------
    issue_loads(0);
    issue_loads(1);
    issue_loads(2);

    for (int c = 0; c < NCHUNKS; c++) {
        CP_WAIT2();          // group c complete (c+1, c+2 still in flight)
        __syncthreads();
        if (c + 3 < NCHUNKS) issue_loads(c + 3);

        uint32_t stg = sb + (c & (NSTAGE - 1)) * STG;
        #pragma unroll
        for (int ks = 0; ks < 2; ks++) {
            uint32_t bP[2][4];
            #pragma unroll
            for (int p = 0; p < 2; p++) {
                uint32_t bo = stg + OFF_B + b_ld
                            + (uint32_t)(ks * 16 * B_STRIDE_B + p * 32);
                ldsm_x4t(bP[p], bo);
            }
            #pragma unroll
            for (int mf = 0; mf < 4; mf++) {
                uint32_t aF[4];
                uint32_t ao = stg + OFF_A + a_ld
                            + (uint32_t)(mf * 16 * A_STRIDE_B + ks * 32);
                ldsm_x4(aF, ao);
                #pragma unroll
                for (int nf = 0; nf < 4; nf++)
                    mma_f16(acc[mf][nf], aF, &bP[nf >> 1][(nf & 1) * 2]);
            }
        }
    }

    // ---------------- epilogue ----------------
    float2 bb[4];
    #pragma unroll
    for (int nf = 0; nf < 4; nf++)
        bb[nf] = *reinterpret_cast<const float2*>(bias + n0 + wn * 32 + nf * 8 + li * 2);

    #pragma unroll
    for (int mf = 0; mf < 4; mf++) {
        #pragma unroll
        for (int half = 0; half < 2; half++) {
            int m = m0 + wm * 64 + mf * 16 + gi + half * 8;
            if (m < Mc) {
                int bimg = m / rpi;
                int r    = m % rpi;
                int gh   = ghb + r / nw;
                int gw   = gwb + r % nw;
                size_t obase = ((size_t)(bimg * (GDIM * GDIM) + gh * GDIM + gw)) * DDIM
                             + n0 + wn * 32 + li * 2;
                #pragma unroll
                for (int nf = 0; nf < 4; nf++) {
                    float2 v;
                    v.x = acc[mf][nf][half * 2 + 0] + bb[nf].x;
                    v.y = acc[mf][nf][half * 2 + 1] + bb[nf].y;
                    *reinterpret_cast<float2*>(out + obase + nf * 8) = v;
                }
            }
        }
    }
}

// ---------------------------------------------------------------------------
extern "C" void kernel_launch(void* const* d_in, const int* in_sizes, int n_in,
                              void* d_out, int out_size) {
    const float* images = (const float*)d_in[0];
    const float* W      = (const float*)d_in[1];
    const float* bias   = (const float*)d_in[2];
    float* out          = (float*)d_out;

    cudaFuncSetAttribute(class_gemm_hmma,
                         cudaFuncAttributeMaxDynamicSharedMemorySize, SMEM_TOTAL);

    prep_kernel<<<CONV_BLOCKS + KCLS, 256>>>(images, W);

    // 100 M-tiles x 6 N-tiles
    dim3 grid(100, DDIM / BN);
    class_gemm_hmma<<<grid, 256, SMEM_TOTAL>>>(bias, out);
}

// round 9
// speedup vs baseline: 2.2352x; 1.0062x over previous
#include <cuda_runtime.h>
#include <cuda_fp16.h>
#include <cstdint>

// ---------------------------------------------------------------------------
// Problem constants
// ---------------------------------------------------------------------------
#define NIMG   64
#define IMGS   224
#define GDIM   14
#define PSZ    16
#define DDIM   768
#define KCLS   768            // per-class K = 16*16*3
#define ROWEL  (IMGS*3)       // 672 elements per image row
#define IMG_ELEMS (NIMG * IMGS * IMGS * 3)   // 9,633,792
#define CONV_BLOCKS (IMG_ELEMS / 8 / 256)    // 4704 (32B per thread)

// GEMM tiling
#define BM      128
#define BN      128
#define BK      64
#define NCHUNKS (KCLS / BK)   // 12

// Scratch: fp16 images (18.4 MB) + fp16 class weights (10.6 MB)
__device__ __align__(16) __half g_img_h[IMG_ELEMS];
__device__ __align__(16) __half g_Bh[9u * KCLS * DDIM];

// ---------------------------------------------------------------------------
// helpers
// ---------------------------------------------------------------------------
__device__ __forceinline__ uint32_t smem_u32(const void* p) {
    uint32_t a;
    asm("{ .reg .u64 t; cvta.to.shared.u64 t, %1; cvt.u32.u64 %0, t; }"
        : "=r"(a) : "l"(p));
    return a;
}

__device__ __forceinline__ void mma_f16(float* c, const uint32_t* a, const uint32_t* b) {
    asm volatile(
        "mma.sync.aligned.m16n8k16.row.col.f32.f16.f16.f32 "
        "{%0,%1,%2,%3}, {%4,%5,%6,%7}, {%8,%9}, {%0,%1,%2,%3};"
        : "+f"(c[0]), "+f"(c[1]), "+f"(c[2]), "+f"(c[3])
        : "r"(a[0]), "r"(a[1]), "r"(a[2]), "r"(a[3]), "r"(b[0]), "r"(b[1]));
}

__device__ __forceinline__ void ldsm_x4(uint32_t* r, uint32_t addr) {
    asm volatile("ldmatrix.sync.aligned.m8n8.x4.shared.b16 {%0,%1,%2,%3}, [%4];"
                 : "=r"(r[0]), "=r"(r[1]), "=r"(r[2]), "=r"(r[3]) : "r"(addr));
}

__device__ __forceinline__ void ldsm_x4t(uint32_t* r, uint32_t addr) {
    asm volatile("ldmatrix.sync.aligned.m8n8.x4.trans.shared.b16 {%0,%1,%2,%3}, [%4];"
                 : "=r"(r[0]), "=r"(r[1]), "=r"(r[2]), "=r"(r[3]) : "r"(addr));
}

#define CP_ASYNC16(dst, src) \
    asm volatile("cp.async.cg.shared.global [%0], [%1], 16;" :: "r"(dst), "l"(src))
#define CP_COMMIT() asm volatile("cp.async.commit_group;" ::: "memory")
#define CP_WAIT1()  asm volatile("cp.async.wait_group 1;" ::: "memory")

// ---------------------------------------------------------------------------
// Kernel 0 (fused prep): blocks [0, CONV_BLOCKS) convert images to fp16
// (32 bytes of fp32 per thread); remaining 768 blocks build per-class fp16
// weights (layout [cls][k][n]).
// ---------------------------------------------------------------------------
__global__ void prep_kernel(const float* __restrict__ img,
                            const float* __restrict__ W) {
    if (blockIdx.x < CONV_BLOCKS) {
        int i = (blockIdx.x * blockDim.x + threadIdx.x) * 2;   // float4 index
        #pragma unroll
        for (int j = 0; j < 2; j++) {
            float4 v = reinterpret_cast<const float4*>(img)[i + j];
            uint32_t p0 = ((uint32_t)__half_as_ushort(__float2half_rn(v.y)) << 16)
                        | __half_as_ushort(__float2half_rn(v.x));
            uint32_t p1 = ((uint32_t)__half_as_ushort(__float2half_rn(v.w)) << 16)
                        | __half_as_ushort(__float2half_rn(v.z));
            reinterpret_cast<uint2*>(g_img_h)[i + j] = make_uint2(p0, p1);
        }
        return;
    }

    int k  = blockIdx.x - CONV_BLOCKS;   // 0..767
    int pp = k / 3,  cin = k % 3;
    int ph = pp >> 4, pw = pp & 15;

    for (int n = threadIdx.x * 2; n < DDIM; n += blockDim.x * 2) {
        const float* wb = W + (size_t)(pp * 15 + cin) * DDIM + n;
        float w0a = wb[0],          w0b = wb[1];
        float w1a = wb[3 * DDIM],   w1b = wb[3 * DDIM + 1];
        float w2a = wb[6 * DDIM],   w2b = wb[6 * DDIM + 1];
        float w3a = wb[9 * DDIM],   w3b = wb[9 * DDIM + 1];
        float w4a = wb[12 * DDIM],  w4b = wb[12 * DDIM + 1];

        #pragma unroll
        for (int cls = 0; cls < 9; cls++) {
            int clsH = cls / 3, clsW = cls % 3;
            int th = (clsH == 0 && ph < 8) ? 0 : (clsH == 2 && ph >= 8) ? 2 : 1;
            int tw = (clsW == 0 && pw < 8) ? 0 : (clsW == 2 && pw >= 8) ? 2 : 1;
            float s0 = w0a, s1 = w0b;
            if (!(th == 2 || tw == 2)) { s0 += w1a; s1 += w1b; }
            if (!(th == 0 || tw == 2)) { s0 += w2a; s1 += w2b; }
            if (!(th == 2 || tw == 0)) { s0 += w3a; s1 += w3b; }
            if (!(th == 0 || tw == 0)) { s0 += w4a; s1 += w4b; }
            uint32_t hv = ((uint32_t)__half_as_ushort(__float2half_rn(s1)) << 16)
                        | __half_as_ushort(__float2half_rn(s0));
            size_t o = ((size_t)cls * KCLS + k) * DDIM + n;
            *reinterpret_cast<uint32_t*>(&g_Bh[o]) = hv;
        }
    }
}

// ---------------------------------------------------------------------------
// Kernel 1: class-partitioned fp16 HMMA GEMM (plain fp16 A and B).
// CTA tile 128x128x768, BK=64, 3-stage cp.async pipeline (12 chunks),
// 8 warps (2m x 4n). 100 M-tiles x 6 N-tiles = 600 CTAs, 2 CTAs/SM.
// ---------------------------------------------------------------------------
#define A_STRIDE_B 144    // bytes per A smem row (64 fp16 + 8 pad)
#define B_STRIDE_B 272    // bytes per B smem row (128 fp16 + 8 pad)
#define OFF_A   0
#define OFF_B   18432     // 128 * 144
#define STG     35840     // 18432 + 64*272
#define NSTAGE  3
#define SMEM_TOTAL (NSTAGE * STG)   // 107520

__global__ __launch_bounds__(256, 2)
void class_gemm_hmma(const float* __restrict__ bias,
                     float* __restrict__ out) {
    extern __shared__ __align__(16) char smem[];
    const uint32_t sb = smem_u32(smem);

    const int nhv[3]  = {1, 12, 1};
    const int ghbv[3] = {0, 1, 13};

    // map blockIdx.x -> (class, local m-tile)
    int mtl = blockIdx.x;
    int cls = 8;
    #pragma unroll
    for (int c = 0; c < 9; c++) {
        int tiles_c = (NIMG * nhv[c / 3] * nhv[c % 3] + BM - 1) / BM;
        if (mtl < tiles_c) { cls = c; break; }
        mtl -= tiles_c;
    }
    const int clsH = cls / 3, clsW = cls % 3;
    const int nw  = nhv[clsW];
    const int ghb = ghbv[clsH], gwb = ghbv[clsW];
    const int rpi = nhv[clsH] * nw;
    const int Mc  = NIMG * rpi;
    const int m0  = mtl * BM;
    const int n0  = blockIdx.y * BN;

    const int t    = threadIdx.x;
    const int wid  = t >> 5, lane = t & 31;
    const int wm   = wid >> 2;        // 0..1 (m)
    const int wn   = wid & 3;         // 0..3 (n)
    const int gi   = lane >> 2;
    const int li   = lane & 3;
    const int l16  = lane & 15;
    const int lhi  = (lane >> 4) & 1;

    // ---- A cp.async mapping: 4 segments per thread (BK=64) ----
    // idx = i*256 + t ; row = idx>>3 (0..127) ; seg = idx&7 (8 k each)
    int arow_[4], aseg_[4];
    uint32_t abase_[4], asz_[4];
    #pragma unroll
    for (int i = 0; i < 4; i++) {
        int idx = i * 256 + t;
        int row = idx >> 3;
        arow_[i] = row;
        aseg_[i] = idx & 7;
        int am = m0 + row;
        bool v = am < Mc;
        int mm = v ? am : 0;
        int bimg = mm / rpi;
        int r    = mm % rpi;
        int gh   = ghb + r / nw;
        int gw   = gwb + r % nw;
        abase_[i] = (uint32_t)((bimg * IMGS + gh * PSZ) * ROWEL + gw * (PSZ * 3));
        asz_[i]   = v ? 16u : 0u;
    }

    const __half* gB = g_Bh + ((size_t)cls * KCLS) * DDIM + n0;

    // ldmatrix base offsets
    const uint32_t a_ld = (uint32_t)((wm * 64 + l16) * A_STRIDE_B + lhi * 16);
    const uint32_t b_ld = (uint32_t)(l16 * B_STRIDE_B + wn * 64 + lhi * 16);

    float acc[4][4][4];
    #pragma unroll
    for (int i = 0; i < 4; i++)
        #pragma unroll
        for (int j = 0; j < 4; j++)
            #pragma unroll
            for (int q = 0; q < 4; q++) acc[i][j][q] = 0.f;

    // ---------------- async tile loader ----------------
    auto issue_loads = [&](int c, uint32_t dst) {
        const int kt = c * BK;
        // A (plain fp16): 4 x 16B per thread
        #pragma unroll
        for (int i = 0; i < 4; i++) {
            int k   = kt + aseg_[i] * 8;
            int phh = k / 48;
            int rem = k - phh * 48;
            const __half* src = g_img_h + abase_[i] + phh * ROWEL + rem;
            uint32_t doff = (uint32_t)(arow_[i] * A_STRIDE_B + aseg_[i] * 16);
            asm volatile("cp.async.cg.shared.global [%0], [%1], 16, %2;"
                         :: "r"(dst + OFF_A + doff), "l"(src), "r"(asz_[i]));
        }
        // B: 4 x 16B per thread
        #pragma unroll
        for (int i = 0; i < 4; i++) {
            int idx = i * 256 + t;
            int row = idx >> 4;          // 0..63
            int seg = idx & 15;
            const __half* src = gB + (size_t)(kt + row) * DDIM + seg * 8;
            uint32_t doff = (uint32_t)(row * B_STRIDE_B + seg * 16);
            CP_ASYNC16(dst + OFF_B + doff, src);
        }
        CP_COMMIT();
    };

    // ---------------- pipeline (3-stage, 2 groups in flight) ----------------
    uint32_t st0 = sb, st1 = sb + STG, st2 = sb + 2 * STG;
    issue_loads(0, st0);
    issue_loads(1, st1);

    for (int c = 0; c < NCHUNKS; c++) {
        CP_WAIT1();          // chunk c complete (c+1 still in flight)
        __syncthreads();
        if (c + 2 < NCHUNKS) issue_loads(c + 2, st2);

        #pragma unroll
        for (int ks = 0; ks < 4; ks++) {
            uint32_t bP[2][4];
            #pragma unroll
            for (int p = 0; p < 2; p++) {
                uint32_t bo = st0 + OFF_B + b_ld
                            + (uint32_t)(ks * 16 * B_STRIDE_B + p * 32);
                ldsm_x4t(bP[p], bo);
            }
            #pragma unroll
            for (int mf = 0; mf < 4; mf++) {
                uint32_t aF[4];
                uint32_t ao = st0 + OFF_A + a_ld
                            + (uint32_t)(mf * 16 * A_STRIDE_B + ks * 32);
                ldsm_x4(aF, ao);
                #pragma unroll
                for (int nf = 0; nf < 4; nf++)
                    mma_f16(acc[mf][nf], aF, &bP[nf >> 1][(nf & 1) * 2]);
            }
        }

        // rotate stages: (c, c+1, c+2) -> (c+1, c+2, c+3)
        uint32_t tmp = st0; st0 = st1; st1 = st2; st2 = tmp;
    }

    // ---------------- epilogue ----------------
    float2 bb[4];
    #pragma unroll
    for (int nf = 0; nf < 4; nf++)
        bb[nf] = *reinterpret_cast<const float2*>(bias + n0 + wn * 32 + nf * 8 + li * 2);

    #pragma unroll
    for (int mf = 0; mf < 4; mf++) {
        #pragma unroll
        for (int half = 0; half < 2; half++) {
            int m = m0 + wm * 64 + mf * 16 + gi + half * 8;
            if (m < Mc) {
                int bimg = m / rpi;
                int r    = m % rpi;
                int gh   = ghb + r / nw;
                int gw   = gwb + r % nw;
                size_t obase = ((size_t)(bimg * (GDIM * GDIM) + gh * GDIM + gw)) * DDIM
                             + n0 + wn * 32 + li * 2;
                #pragma unroll
                for (int nf = 0; nf < 4; nf++) {
                    float2 v;
                    v.x = acc[mf][nf][half * 2 + 0] + bb[nf].x;
                    v.y = acc[mf][nf][half * 2 + 1] + bb[nf].y;
                    *reinterpret_cast<float2*>(out + obase + nf * 8) = v;
                }
            }
        }
    }
}

// ---------------------------------------------------------------------------
extern "C" void kernel_launch(void* const* d_in, const int* in_sizes, int n_in,
                              void* d_out, int out_size) {
    const float* images = (const float*)d_in[0];
    const float* W      = (const float*)d_in[1];
    const float* bias   = (const float*)d_in[2];
    float* out          = (float*)d_out;

    cudaFuncSetAttribute(class_gemm_hmma,
                         cudaFuncAttributeMaxDynamicSharedMemorySize, SMEM_TOTAL);

    prep_kernel<<<CONV_BLOCKS + KCLS, 256>>>(images, W);

    // 100 M-tiles x 6 N-tiles
    dim3 grid(100, DDIM / BN);
    class_gemm_hmma<<<grid, 256, SMEM_TOTAL>>>(bias, out);
}